// round 13
// baseline (speedup 1.0000x reference)
#include <cuda_runtime.h>
#include <math.h>

#define NTOK   65536
#define EXPN   64
#define DIMK   2048
#define NITERS 20
#define KACT   8
#define MAXG   512
#define BK     32
#define NSLICE 4
#define KSLICE (DIMK / NSLICE)          // 512
#define SNW    16                       // sinkhorn warps per CTA

typedef unsigned long long ull;

// Scratch (static __device__ arrays: no allocations allowed)
__device__ float  g_A[(size_t)NTOK * EXPN];          // 67 MB: la = -logits/0.05
__device__ double g_partials[2][MAXG][EXPN];         // per-CTA column partial sums (fp64)
__device__ double g_loss_part[MAXG][EXPN];           // per-CTA final pi column sums (fp64)
__device__ ull    g_arrive;                          // grid barrier (monotonic across replays)
__device__ ull    g_release;

// ---------------------------------------------------------------------------
// packed f32x2 helpers (each lane is an IEEE-754 fp32 op: packed chains are
// bit-identical to per-lane scalar chains)
// ---------------------------------------------------------------------------
__device__ __forceinline__ ull pack2(float x){
    ull r; unsigned u = __float_as_uint(x);
    asm("mov.b64 %0, {%1, %1};" : "=l"(r) : "r"(u));
    return r;
}
__device__ __forceinline__ void unpack2(ull v, float &lo, float &hi){
    unsigned a, b;
    asm("mov.b64 {%0, %1}, %2;" : "=r"(a), "=r"(b) : "l"(v));
    lo = __uint_as_float(a); hi = __uint_as_float(b);
}
__device__ __forceinline__ void fma2acc(ull &d, ull a, ull b){
    asm("fma.rn.f32x2 %0, %1, %2, %0;" : "+l"(d) : "l"(a), "l"(b));
}
__device__ __forceinline__ ull add2(ull a, ull b){
    ull d; asm("add.rn.f32x2 %0, %1, %2;" : "=l"(d) : "l"(a), "l"(b)); return d;
}

// ---------------------------------------------------------------------------
// GEMM emulating cuBLAS sliced1x4 accumulation (BITWISE-FROZEN semantics):
//   K split into 4 CONTIGUOUS chunks of 512; each chunk is a sequential
//   ascending-k fp32 FFMA chain; partials combined (S0+S2)+(S1+S3); then
//   la = (-L)/0.05f (IEEE rn div).
// Schedule change vs R10: w is stored PRE-DUPLICATED as packed ull in SMEM,
// removing the per-k pack2 MOVs from the inner loop (values & chain order
// unchanged -> identical bits). Inner loop: 3x LDS.128 + 8x FFMA2.
// ---------------------------------------------------------------------------
__global__ __launch_bounds__(512) void gemm_kernel(const float* __restrict__ x,
                                                   const float* __restrict__ w){
    __shared__ __align__(16) float sx[BK][132];   // [k][token]
    __shared__ __align__(16) ull   sw2[BK][66];   // [k][expert] duplicated pairs

    int tid = threadIdx.x;
    int m0  = blockIdx.x * 128;
    int tx  = tid & 15;          // experts tx*4 .. tx*4+3
    int ty  = tid >> 4;          // tokens  ty*4 .. ty*4+3 (0..31)

    ull acc[8];                  // current chunk: [pair(2)][expert(4)]
    ull sv[3][8];                // snapshots of chunks 0..2

    #pragma unroll
    for (int i = 0; i < 8; i++) acc[i] = 0ULL;

    #pragma unroll
    for (int c = 0; c < NSLICE; c++){
        for (int t = 0; t < KSLICE / BK; t++){     // 16 tiles per chunk
            int k0 = c * KSLICE + t * BK;
            // x tile: 128 rows x 32 k = 1024 float4 -> 2 per thread (transposed)
            #pragma unroll
            for (int i = 0; i < 2; i++){
                int f4  = tid + i * 512;
                int row = f4 >> 3, kq = f4 & 7;
                float4 v = *(const float4*)(x + (size_t)(m0 + row) * DIMK + k0 + kq * 4);
                sx[kq*4+0][row] = v.x; sx[kq*4+1][row] = v.y;
                sx[kq*4+2][row] = v.z; sx[kq*4+3][row] = v.w;
            }
            // w tile: 64 rows x 32 k = 512 float4 -> 1 per thread, duplicated
            {
                int row = tid >> 3, kq = tid & 7;
                float4 v = *(const float4*)(w + (size_t)row * DIMK + k0 + kq * 4);
                sw2[kq*4+0][row] = pack2(v.x); sw2[kq*4+1][row] = pack2(v.y);
                sw2[kq*4+2][row] = pack2(v.z); sw2[kq*4+3][row] = pack2(v.w);
            }
            __syncthreads();

            #pragma unroll
            for (int k = 0; k < BK; k++){          // ascending k within chunk
                ulonglong2 A01 = *(const ulonglong2*)&sx[k][ty*4];
                ulonglong2 B01 = *(const ulonglong2*)&sw2[k][tx*4];
                ulonglong2 B23 = *(const ulonglong2*)&sw2[k][tx*4 + 2];
                fma2acc(acc[0], A01.x, B01.x);
                fma2acc(acc[1], A01.x, B01.y);
                fma2acc(acc[2], A01.x, B23.x);
                fma2acc(acc[3], A01.x, B23.y);
                fma2acc(acc[4], A01.y, B01.x);
                fma2acc(acc[5], A01.y, B01.y);
                fma2acc(acc[6], A01.y, B23.x);
                fma2acc(acc[7], A01.y, B23.y);
            }
            __syncthreads();
        }
        if (c < NSLICE - 1){
            #pragma unroll
            for (int i = 0; i < 8; i++){ sv[c][i] = acc[i]; acc[i] = 0ULL; }
        }
    }

    // combine slices: (S0+S2)+(S1+S3), IEEE per packed lane; la = (-L)/0.05f
    #pragma unroll
    for (int p = 0; p < 2; p++){
        float la_lo[4], la_hi[4];
        #pragma unroll
        for (int e = 0; e < 4; e++){
            ull S0 = sv[0][p*4+e], S1 = sv[1][p*4+e];
            ull S2 = sv[2][p*4+e], S3 = acc[p*4+e];
            ull L2 = add2(add2(S0, S2), add2(S1, S3));
            float L0, L1;
            unpack2(L2, L0, L1);
            la_lo[e] = __fdiv_rn(-L0, 0.05f);
            la_hi[e] = __fdiv_rn(-L1, 0.05f);
        }
        size_t rlo = (size_t)(m0 + ty*4 + p) * EXPN + tx*4;   // p selects lane row
        // NOTE: packed lane0 = token ty*4+2p? keep same mapping as R10:
        // pair p covers tokens (ty*4 + 2p) and (ty*4 + 2p + 1)
        rlo = (size_t)(m0 + ty*4 + 2*p) * EXPN + tx*4;
        *(float4*)(g_A + rlo)        = make_float4(la_lo[0], la_lo[1], la_lo[2], la_lo[3]);
        *(float4*)(g_A + rlo + EXPN) = make_float4(la_hi[0], la_hi[1], la_hi[2], la_hi[3]);
    }
}

// ---------------------------------------------------------------------------
// software grid barrier (1 CTA/SM by SMEM, grid == #SMs -> all co-resident)
// ---------------------------------------------------------------------------
__device__ __forceinline__ void grid_barrier(int G){
    __syncthreads();
    if (threadIdx.x == 0){
        __threadfence();
        ull t = atomicAdd(&g_arrive, 1ULL) + 1ULL;
        ull epoch = (t - 1ULL) / (ull)G + 1ULL;
        if (t % (ull)G == 0ULL){
            atomicExch(&g_release, epoch);
        } else {
            unsigned ns = 32;
            while (atomicAdd(&g_release, 0ULL) < epoch){
                __nanosleep(ns);
                if (ns < 256) ns <<= 1;
            }
        }
        __threadfence();
    }
    __syncthreads();
}

// ---------------------------------------------------------------------------
// Persistent Sinkhorn, 512 threads (16 warps -> 4/SMSP for latency hiding):
//   per iteration: la -= (logf(sum_row expf(la-m)) + m)   (fp32 sub, stored)
//                  la -= c_e  (folded into next pass's read, same rounding)
// Column sums REUSE the row-pass exponentials: contribution e*(1/s) in fp32,
// accumulated per-lane in fp64, combined cross-warp/CTA fp64 in fixed order
// (<=1ulp change to c_e vs R10; flip-neutral class). Row trajectory (stored
// w) and epilogue pi = expf(la-c) stay on accurate libdevice expf/logf.
// ---------------------------------------------------------------------------
__global__ __launch_bounds__(512, 1) void sinkhorn_kernel(
        float* __restrict__ out, int G, int rowsPer,
        long long idxBase, long long lossBase, int writeDisp)
{
    extern __shared__ float sA[];                 // rowsPer x 64
    __shared__ double sredd[SNW][EXPN];
    int tid  = threadIdx.x;
    int lane = tid & 31;
    int warp = tid >> 5;
    int bid  = blockIdx.x;
    int row0 = bid * rowsPer;
    int nrows = NTOK - row0;
    if (nrows > rowsPer) nrows = rowsPer;
    if (nrows < 0) nrows = 0;

    {
        const float4* src = (const float4*)(g_A + (size_t)row0 * EXPN);
        float4* dst = (float4*)sA;
        int nf4 = nrows * (EXPN / 4);
        for (int i = tid; i < nf4; i += 512) dst[i] = src[i];
    }
    __syncthreads();

    float c0 = 0.f, c1 = 0.f;

    for (int it = 0; it < NITERS; it++){
        double ca0 = 0.0, ca1 = 0.0;
        for (int r = warp; r < nrows; r += SNW){
            float v0 = sA[r*EXPN + lane]      - c0;
            float v1 = sA[r*EXPN + lane + 32] - c1;
            float m = fmaxf(v0, v1);
            #pragma unroll
            for (int o = 16; o; o >>= 1) m = fmaxf(m, __shfl_xor_sync(0xffffffffu, m, o));
            float e0 = expf(v0 - m);
            float e1 = expf(v1 - m);
            float s = e0 + e1;
            #pragma unroll
            for (int o = 16; o; o >>= 1) s += __shfl_xor_sync(0xffffffffu, s, o);
            float rn = logf(s) + m;
            sA[r*EXPN + lane]      = v0 - rn;
            sA[r*EXPN + lane + 32] = v1 - rn;
            float inv = 1.0f / s;                 // IEEE div
            ca0 += (double)(e0 * inv);            // == exp(w) to ~1ulp
            ca1 += (double)(e1 * inv);
        }
        sredd[warp][lane] = ca0; sredd[warp][lane + 32] = ca1;
        __syncthreads();
        if (warp == 0){
            double t0 = 0.0, t1 = 0.0;
            #pragma unroll
            for (int ww = 0; ww < SNW; ww++){ t0 += sredd[ww][lane]; t1 += sredd[ww][lane+32]; }
            g_partials[it & 1][bid][lane]      = t0;
            g_partials[it & 1][bid][lane + 32] = t1;
        }
        grid_barrier(G);
        {
            double S0 = 0.0, S1 = 0.0;
            for (int b = warp; b < G; b += SNW){
                S0 += g_partials[it & 1][b][lane];
                S1 += g_partials[it & 1][b][lane + 32];
            }
            sredd[warp][lane] = S0; sredd[warp][lane + 32] = S1;
            __syncthreads();
            S0 = 0.0; S1 = 0.0;
            #pragma unroll
            for (int ww = 0; ww < SNW; ww++){ S0 += sredd[ww][lane]; S1 += sredd[ww][lane+32]; }
            c0 = (float)log(S0);
            c1 = (float)log(S1);
            __syncthreads();
        }
    }

    double ls0 = 0.0, ls1 = 0.0;
    for (int r = warp; r < nrows; r += SNW){
        size_t n = (size_t)(row0 + r);
        float la0 = sA[r*EXPN + lane]      - c0;
        float la1 = sA[r*EXPN + lane + 32] - c1;
        float p0 = expf(la0);
        float p1 = expf(la1);
        if (writeDisp){
            out[n*EXPN + lane]      = p0;
            out[n*EXPN + lane + 32] = p1;
        }
        ls0 += (double)p0; ls1 += (double)p1;
        if (idxBase >= 0){
            // key = (value_bits << 32) | (63 - idx): ties -> smallest index
            ull k0 = ((ull)__float_as_uint(p0) << 32) | (ull)(63 - lane);
            ull k1 = ((ull)__float_as_uint(p1) << 32) | (ull)(31 - lane);
            #pragma unroll
            for (int j = 0; j < KACT; j++){
                ull b = k0 > k1 ? k0 : k1;
                #pragma unroll
                for (int o = 16; o; o >>= 1){
                    ull ob = __shfl_xor_sync(0xffffffffu, b, o);
                    if (ob > b) b = ob;
                }
                if (lane == j)
                    out[(size_t)idxBase + n*KACT + j] = (float)(63 - (int)(b & 63ULL));
                if (k0 == b) k0 = 0ULL;
                if (k1 == b) k1 = 0ULL;
            }
        }
    }

    sredd[warp][lane] = ls0; sredd[warp][lane + 32] = ls1;
    __syncthreads();
    if (warp == 0){
        double t0 = 0.0, t1 = 0.0;
        #pragma unroll
        for (int ww = 0; ww < SNW; ww++){ t0 += sredd[ww][lane]; t1 += sredd[ww][lane+32]; }
        g_loss_part[bid][lane]      = t0;
        g_loss_part[bid][lane + 32] = t1;
    }
    grid_barrier(G);

    if (lossBase >= 0 && bid == 0){
        double S0 = 0.0, S1 = 0.0;
        for (int b = warp; b < G; b += SNW){
            S0 += g_loss_part[b][lane];
            S1 += g_loss_part[b][lane + 32];
        }
        sredd[warp][lane] = S0; sredd[warp][lane + 32] = S1;
        __syncthreads();
        if (tid == 0){
            const double u  = 1.0 / EXPN;
            const double lu = log(u);
            double loss = 0.0;
            for (int e = 0; e < EXPN; e++){
                double S = 0.0;
                #pragma unroll
                for (int ww = 0; ww < SNW; ww++) S += sredd[ww][e];
                double load = S / (double)NTOK;
                loss += u * (lu - log(load));
            }
            out[lossBase] = (float)loss;
        }
    }
}

// ---------------------------------------------------------------------------
extern "C" void kernel_launch(void* const* d_in, const int* in_sizes, int n_in,
                              void* d_out, int out_size){
    (void)in_sizes; (void)n_in;
    const float* x = (const float*)d_in[0];     // (8,8192,2048) f32
    const float* w = (const float*)d_in[1];     // (64,2048) f32
    float* out = (float*)d_out;

    int G = 148;
    cudaDeviceGetAttribute(&G, cudaDevAttrMultiProcessorCount, 0);
    if (G < 1)    G = 148;
    if (G > MAXG) G = MAXG;
    int rowsPer = (NTOK + G - 1) / G;
    size_t smem = (size_t)rowsPer * EXPN * sizeof(float);
    cudaFuncSetAttribute(sinkhorn_kernel,
                         cudaFuncAttributeMaxDynamicSharedMemorySize, (int)smem);

    // adaptive output layout: [dispatch (N*64)] [indices (N*8) as f32] [loss]
    const long long ND = (long long)NTOK * EXPN;
    const long long NI = (long long)NTOK * KACT;
    long long idxBase = -1, lossBase = -1;
    int writeDisp = 0;
    long long osz = (long long)out_size;
    if (osz >= ND + NI){
        writeDisp = 1; idxBase = ND;
        if (osz > ND + NI) lossBase = ND + NI;
    } else if (osz >= ND){
        writeDisp = 1;
        if (osz > ND) lossBase = ND;
    } else if (osz >= NI){
        idxBase = 0;
        if (osz > NI) lossBase = NI;
    }

    gemm_kernel<<<NTOK/128, 512>>>(x, w);
    sinkhorn_kernel<<<G, 512, (unsigned)smem>>>(out, G, rowsPer,
                                                idxBase, lossBase, writeDisp);
}

// round 14
// speedup vs baseline: 2.5008x; 2.5008x over previous
#include <cuda_runtime.h>
#include <math.h>

#define NTOK   65536
#define EXPN   64
#define DIMK   2048
#define NITERS 20
#define KACT   8
#define MAXG   512
#define BK     32
#define NSLICE 4
#define KSLICE (DIMK / NSLICE)          // 512
#define SNW    8                        // sinkhorn warps per CTA
#define LOG2E  1.4426950408889634f

typedef unsigned long long ull;

// Scratch (static __device__ arrays: no allocations allowed)
__device__ float g_A[(size_t)NTOK * EXPN];          // 67 MB: la = -logits/0.05
__device__ float g_partials[2][MAXG][EXPN];         // per-CTA column partial sums
__device__ float g_loss_part[MAXG][EXPN];           // per-CTA final pi column sums
__device__ ull   g_arrive;                          // grid barrier (monotonic across replays)
__device__ ull   g_release;

// ---------------------------------------------------------------------------
// packed f32x2 helpers (each lane is an IEEE-754 fp32 op: packed chains are
// bit-identical to per-lane scalar chains)
// ---------------------------------------------------------------------------
__device__ __forceinline__ ull pack2(float x){
    ull r; unsigned u = __float_as_uint(x);
    asm("mov.b64 %0, {%1, %1};" : "=l"(r) : "r"(u));
    return r;
}
__device__ __forceinline__ void unpack2(ull v, float &lo, float &hi){
    unsigned a, b;
    asm("mov.b64 {%0, %1}, %2;" : "=r"(a), "=r"(b) : "l"(v));
    lo = __uint_as_float(a); hi = __uint_as_float(b);
}
__device__ __forceinline__ void fma2acc(ull &d, ull a, ull b){
    asm("fma.rn.f32x2 %0, %1, %2, %0;" : "+l"(d) : "l"(a), "l"(b));
}
__device__ __forceinline__ ull add2(ull a, ull b){
    ull d; asm("add.rn.f32x2 %0, %1, %2;" : "=l"(d) : "l"(a), "l"(b)); return d;
}
// fast MUFU ops for sinkhorn iterations (flip-neutral; dispatch headroom huge)
__device__ __forceinline__ float ex2f(float x){
    float y; asm("ex2.approx.ftz.f32 %0, %1;" : "=f"(y) : "f"(x)); return y;
}
__device__ __forceinline__ float lg2f(float x){
    float y; asm("lg2.approx.f32 %0, %1;" : "=f"(y) : "f"(x)); return y;
}
__device__ __forceinline__ float rcpf(float x){
    float y; asm("rcp.approx.ftz.f32 %0, %1;" : "=f"(y) : "f"(x)); return y;
}

// ---------------------------------------------------------------------------
// GEMM emulating cuBLAS sliced1x4 accumulation (BITWISE-FROZEN semantics,
// identical to the R10 passing kernel):
//   K in 4 CONTIGUOUS 512-chunks; each chunk a sequential ascending-k fp32
//   FFMA chain per output; combine (S0+S2)+(S1+S3); la = (-L)/0.05f.
// Schedule: 256 threads, 8 tokens x 4 experts per thread = 16 packed FMA2
// per k (higher FMA density). S0+=S2 folded early to cap register pressure.
// ---------------------------------------------------------------------------
__global__ __launch_bounds__(256) void gemm_kernel(const float* __restrict__ x,
                                                   const float* __restrict__ w){
    __shared__ __align__(16) float sx[BK][132];   // [k][token]
    __shared__ __align__(16) float sw[BK][68];    // [k][expert]

    int tid = threadIdx.x;
    int m0  = blockIdx.x * 128;
    int tx  = tid & 15;          // experts tx*4 .. tx*4+3
    int ty  = tid >> 4;          // tokens  ty*8 .. ty*8+7 (4 pairs)

    ull acc[16];                 // current chunk: [pair(4)][expert(4)]
    ull S0[16], S1[16];

    #pragma unroll
    for (int i = 0; i < 16; i++) acc[i] = 0ULL;

    #pragma unroll
    for (int c = 0; c < NSLICE; c++){
        for (int t = 0; t < KSLICE / BK; t++){     // 16 tiles per chunk
            int k0 = c * KSLICE + t * BK;
            // x tile: 128 rows x 32 k = 1024 float4 -> 4 per thread (transposed)
            #pragma unroll
            for (int i = 0; i < 4; i++){
                int f4  = tid + i * 256;
                int row = f4 >> 3, kq = f4 & 7;
                float4 v = *(const float4*)(x + (size_t)(m0 + row) * DIMK + k0 + kq * 4);
                sx[kq*4+0][row] = v.x; sx[kq*4+1][row] = v.y;
                sx[kq*4+2][row] = v.z; sx[kq*4+3][row] = v.w;
            }
            // w tile: 64 rows x 32 k = 512 float4 -> 2 per thread
            #pragma unroll
            for (int i = 0; i < 2; i++){
                int f4  = tid + i * 256;
                int row = f4 >> 3, kq = f4 & 7;
                float4 v = *(const float4*)(w + (size_t)row * DIMK + k0 + kq * 4);
                sw[kq*4+0][row] = v.x; sw[kq*4+1][row] = v.y;
                sw[kq*4+2][row] = v.z; sw[kq*4+3][row] = v.w;
            }
            __syncthreads();

            #pragma unroll
            for (int k = 0; k < BK; k++){          // ascending k within chunk
                ulonglong2 A01 = *(const ulonglong2*)&sx[k][ty*8];
                ulonglong2 A23 = *(const ulonglong2*)&sx[k][ty*8 + 4];
                ull ap[4] = {A01.x, A01.y, A23.x, A23.y};
                float4 b4 = *(const float4*)&sw[k][tx*4];
                ull bp[4] = {pack2(b4.x), pack2(b4.y), pack2(b4.z), pack2(b4.w)};
                #pragma unroll
                for (int p = 0; p < 4; p++)
                    #pragma unroll
                    for (int e = 0; e < 4; e++)
                        fma2acc(acc[p*4+e], ap[p], bp[e]);
            }
            __syncthreads();
        }
        if (c == 0){
            #pragma unroll
            for (int i = 0; i < 16; i++){ S0[i] = acc[i]; acc[i] = 0ULL; }
        } else if (c == 1){
            #pragma unroll
            for (int i = 0; i < 16; i++){ S1[i] = acc[i]; acc[i] = 0ULL; }
        } else if (c == 2){
            #pragma unroll
            for (int i = 0; i < 16; i++){ S0[i] = add2(S0[i], acc[i]); acc[i] = 0ULL; }
        }
    }

    // combine: (S0+S2)+(S1+S3)  (S0 already holds S0+S2); la = (-L)/0.05f
    #pragma unroll
    for (int p = 0; p < 4; p++){
        float la_lo[4], la_hi[4];
        #pragma unroll
        for (int e = 0; e < 4; e++){
            ull L2 = add2(S0[p*4+e], add2(S1[p*4+e], acc[p*4+e]));
            float L0, L1;
            unpack2(L2, L0, L1);
            la_lo[e] = __fdiv_rn(-L0, 0.05f);
            la_hi[e] = __fdiv_rn(-L1, 0.05f);
        }
        size_t rlo = (size_t)(m0 + ty*8 + 2*p) * EXPN + tx*4;
        *(float4*)(g_A + rlo)        = make_float4(la_lo[0], la_lo[1], la_lo[2], la_lo[3]);
        *(float4*)(g_A + rlo + EXPN) = make_float4(la_hi[0], la_hi[1], la_hi[2], la_hi[3]);
    }
}

// ---------------------------------------------------------------------------
// software grid barrier (1 CTA/SM by SMEM, grid == #SMs -> all co-resident)
// ---------------------------------------------------------------------------
__device__ __forceinline__ void grid_barrier(int G){
    __syncthreads();
    if (threadIdx.x == 0){
        __threadfence();
        ull t = atomicAdd(&g_arrive, 1ULL) + 1ULL;
        ull epoch = (t - 1ULL) / (ull)G + 1ULL;
        if (t % (ull)G == 0ULL){
            atomicExch(&g_release, epoch);
        } else {
            unsigned ns = 32;
            while (atomicAdd(&g_release, 0ULL) < epoch){
                __nanosleep(ns);
                if (ns < 256) ns <<= 1;
            }
        }
        __threadfence();
    }
    __syncthreads();
}

// ---------------------------------------------------------------------------
// Persistent Sinkhorn, rank-1 potential form (R3 structure: proven dispatch
// ~5.8e-6 and flip-neutral). sA holds la*log2e, NEVER rewritten until the
// last iteration. Per iteration only c_e (base-2 col potential) evolves:
//   p[n,e] = exp2(A - c - m_n) / rowsum ; c += log2(colsum(p))
// Fast MUFU ex2/lg2/rcp, fp32 fixed-order deterministic reductions,
// 2-row interleave for ILP. ONE grid barrier per iteration.
// ---------------------------------------------------------------------------
__global__ __launch_bounds__(256, 1) void sinkhorn_kernel(
        float* __restrict__ out, int G, int rowsPer,
        long long idxBase, long long lossBase, int writeDisp)
{
    extern __shared__ float sA[];                 // rowsPer x 64
    __shared__ float sred[SNW][EXPN];
    int tid  = threadIdx.x;
    int lane = tid & 31;
    int warp = tid >> 5;
    int bid  = blockIdx.x;
    int row0 = bid * rowsPer;
    int nrows = NTOK - row0;
    if (nrows > rowsPer) nrows = rowsPer;
    if (nrows < 0) nrows = 0;

    // load this CTA's chunk, pre-scaled to base-2
    {
        const float4* src = (const float4*)(g_A + (size_t)row0 * EXPN);
        float4* dst = (float4*)sA;
        int nf4 = nrows * (EXPN / 4);
        for (int i = tid; i < nf4; i += 256){
            float4 v = src[i];
            v.x *= LOG2E; v.y *= LOG2E; v.z *= LOG2E; v.w *= LOG2E;
            dst[i] = v;
        }
    }
    __syncthreads();

    float c0 = 0.f, c1 = 0.f;        // base-2 column potentials
    float icol0 = 0.f, icol1 = 0.f;

    for (int it = 0; it < NITERS; it++){
        const bool last = (it == NITERS - 1);
        float ca0 = 0.f, ca1 = 0.f;
        for (int r = warp*2; r < nrows; r += 2*SNW){
            int r2 = r + 1;
            bool two = (r2 < nrows);
            float a0 = sA[r*EXPN + lane]      - c0;
            float a1 = sA[r*EXPN + lane + 32] - c1;
            float b0 = two ? (sA[r2*EXPN + lane]      - c0) : 0.f;
            float b1 = two ? (sA[r2*EXPN + lane + 32] - c1) : 0.f;
            float ma = fmaxf(a0, a1);
            float mb = fmaxf(b0, b1);
            #pragma unroll
            for (int o = 16; o; o >>= 1){
                ma = fmaxf(ma, __shfl_xor_sync(0xffffffffu, ma, o));
                mb = fmaxf(mb, __shfl_xor_sync(0xffffffffu, mb, o));
            }
            float ea0 = ex2f(a0 - ma), ea1 = ex2f(a1 - ma);
            float eb0 = ex2f(b0 - mb), eb1 = ex2f(b1 - mb);
            float sa = ea0 + ea1, sb = eb0 + eb1;
            #pragma unroll
            for (int o = 16; o; o >>= 1){
                sa += __shfl_xor_sync(0xffffffffu, sa, o);
                sb += __shfl_xor_sync(0xffffffffu, sb, o);
            }
            float ia = rcpf(sa), ib = rcpf(sb);
            float pa0 = ea0 * ia, pa1 = ea1 * ia;
            float pb0 = eb0 * ib, pb1 = eb1 * ib;
            ca0 += pa0; ca1 += pa1;
            if (two){ ca0 += pb0; ca1 += pb1; }
            if (last){
                sA[r*EXPN + lane]      = pa0;
                sA[r*EXPN + lane + 32] = pa1;
                if (two){
                    sA[r2*EXPN + lane]      = pb0;
                    sA[r2*EXPN + lane + 32] = pb1;
                }
            }
        }
        // CTA column reduce (fixed order) -> deterministic per-CTA slot
        sred[warp][lane] = ca0; sred[warp][lane + 32] = ca1;
        __syncthreads();
        if (warp == 0){
            float t0 = 0.f, t1 = 0.f;
            #pragma unroll
            for (int ww = 0; ww < SNW; ww++){ t0 += sred[ww][lane]; t1 += sred[ww][lane+32]; }
            g_partials[it & 1][bid][lane]      = t0;
            g_partials[it & 1][bid][lane + 32] = t1;
        }
        grid_barrier(G);
        // every CTA sums all partials in a fixed order (identical c everywhere)
        {
            float S0 = 0.f, S1 = 0.f;
            for (int b = warp; b < G; b += SNW){
                S0 += g_partials[it & 1][b][lane];
                S1 += g_partials[it & 1][b][lane + 32];
            }
            sred[warp][lane] = S0; sred[warp][lane + 32] = S1;
            __syncthreads();
            S0 = 0.f; S1 = 0.f;
            #pragma unroll
            for (int ww = 0; ww < SNW; ww++){ S0 += sred[ww][lane]; S1 += sred[ww][lane+32]; }
            if (!last){ c0 += lg2f(S0); c1 += lg2f(S1); }
            else      { icol0 = rcpf(S0); icol1 = rcpf(S1); }
            __syncthreads();
        }
    }

    // ---- epilogue: pi = p * icol ; dispatch, stable top-8, loss partials ----
    float ls0 = 0.f, ls1 = 0.f;
    for (int r = warp; r < nrows; r += SNW){
        size_t n = (size_t)(row0 + r);
        float p0 = sA[r*EXPN + lane]      * icol0;
        float p1 = sA[r*EXPN + lane + 32] * icol1;
        if (writeDisp){
            out[n*EXPN + lane]      = p0;
            out[n*EXPN + lane + 32] = p1;
        }
        ls0 += p0; ls1 += p1;
        if (idxBase >= 0){
            // key = (value_bits << 32) | (63 - idx): ties -> smallest index
            ull k0 = ((ull)__float_as_uint(p0) << 32) | (ull)(63 - lane);
            ull k1 = ((ull)__float_as_uint(p1) << 32) | (ull)(31 - lane);
            #pragma unroll
            for (int j = 0; j < KACT; j++){
                ull b = k0 > k1 ? k0 : k1;
                #pragma unroll
                for (int o = 16; o; o >>= 1){
                    ull ob = __shfl_xor_sync(0xffffffffu, b, o);
                    if (ob > b) b = ob;
                }
                if (lane == j)
                    out[(size_t)idxBase + n*KACT + j] = (float)(63 - (int)(b & 63ULL));
                if (k0 == b) k0 = 0ULL;
                if (k1 == b) k1 = 0ULL;
            }
        }
    }

    sred[warp][lane] = ls0; sred[warp][lane + 32] = ls1;
    __syncthreads();
    if (warp == 0){
        float t0 = 0.f, t1 = 0.f;
        #pragma unroll
        for (int ww = 0; ww < SNW; ww++){ t0 += sred[ww][lane]; t1 += sred[ww][lane+32]; }
        g_loss_part[bid][lane]      = t0;
        g_loss_part[bid][lane + 32] = t1;
    }
    grid_barrier(G);

    if (lossBase >= 0 && bid == 0){
        float S0 = 0.f, S1 = 0.f;
        for (int b = warp; b < G; b += SNW){
            S0 += g_loss_part[b][lane];
            S1 += g_loss_part[b][lane + 32];
        }
        sred[warp][lane] = S0; sred[warp][lane + 32] = S1;
        __syncthreads();
        if (tid == 0){
            const double u  = 1.0 / EXPN;
            const double lu = log(u);
            double loss = 0.0;
            for (int e = 0; e < EXPN; e++){
                double S = 0.0;
                #pragma unroll
                for (int ww = 0; ww < SNW; ww++) S += (double)sred[ww][e];
                double load = S / (double)NTOK;
                loss += u * (lu - log(load));
            }
            out[lossBase] = (float)loss;
        }
    }
}

// ---------------------------------------------------------------------------
extern "C" void kernel_launch(void* const* d_in, const int* in_sizes, int n_in,
                              void* d_out, int out_size){
    (void)in_sizes; (void)n_in;
    const float* x = (const float*)d_in[0];     // (8,8192,2048) f32
    const float* w = (const float*)d_in[1];     // (64,2048) f32
    float* out = (float*)d_out;

    int G = 148;
    cudaDeviceGetAttribute(&G, cudaDevAttrMultiProcessorCount, 0);
    if (G < 1)    G = 148;
    if (G > MAXG) G = MAXG;
    int rowsPer = (NTOK + G - 1) / G;
    size_t smem = (size_t)rowsPer * EXPN * sizeof(float);
    cudaFuncSetAttribute(sinkhorn_kernel,
                         cudaFuncAttributeMaxDynamicSharedMemorySize, (int)smem);

    // adaptive output layout: [dispatch (N*64)] [indices (N*8) as f32] [loss]
    const long long ND = (long long)NTOK * EXPN;
    const long long NI = (long long)NTOK * KACT;
    long long idxBase = -1, lossBase = -1;
    int writeDisp = 0;
    long long osz = (long long)out_size;
    if (osz >= ND + NI){
        writeDisp = 1; idxBase = ND;
        if (osz > ND + NI) lossBase = ND + NI;
    } else if (osz >= ND){
        writeDisp = 1;
        if (osz > ND) lossBase = ND;
    } else if (osz >= NI){
        idxBase = 0;
        if (osz > NI) lossBase = NI;
    }

    gemm_kernel<<<NTOK/128, 256>>>(x, w);
    sinkhorn_kernel<<<G, 256, (unsigned)smem>>>(out, G, rowsPer,
                                                idxBase, lossBase, writeDisp);
}